// round 9
// baseline (speedup 1.0000x reference)
#include <cuda_runtime.h>
#include <cuda_fp16.h>
#include <cstdint>

// ---------------- problem constants ----------------
#define Bb   256
#define Tt   512
#define Ii   64
#define Hh   512
#define NTHR 288     // 8 compute warps (2M x 2N x 2Ksplit, tile M32xN32) + 1 DMA warp

// SMEM layout offsets (from 1024-aligned base)
#define OFF_WHHI 0            // W_hh slice hi (fp16): [64 c][1024 B]
#define OFF_WHLO 65536        // W_hh slice lo (fp16)
#define OFF_WXHI 131072       // W_ih slice hi: [64 c][128 B]
#define OFF_WXLO 139264
#define OFF_A0   147456       // h chunk buf 0: 16KB (fp16)
#define OFF_A1   163840       // contiguous with A0
#define OFF_XB   180224       // x buf: 8KB (scratch spans A0+A1+XB = 40KB)
#define DSM_BYTES (188416 + 1024)

// ---------------- persistent device state ----------------
// h tile layout: [buf][group][kchunk][16KB]; group = half*2 + mtile (64 batch rows)
// chunk = 64 rows x 128 units fp16 (256B/row), 16B-chunk swizzle
__device__ __align__(1024) unsigned char g_hblk[2][4][4][16384];
// x tile layout: [t][group][8KB] = 64 rows x 64 fp16 (128B/row), swizzled
__device__ __align__(1024) unsigned char g_xblk[Tt][4][8192];
__device__ float    g_hfinal[Bb][Hh];
__device__ unsigned g_cnt[4][4][16];   // [group][kchunk], padded to 64B

// ---------------- PTX helpers ----------------
__device__ __forceinline__ uint32_t smem_u32(const void* p) {
    uint32_t a;
    asm("{ .reg .u64 t; cvta.to.shared.u64 t, %1; cvt.u32.u64 %0, t; }" : "=r"(a) : "l"(p));
    return a;
}
#define MBARRIER_INIT(sa, cnt) \
    asm volatile("mbarrier.init.shared.b64 [%0], %1;" :: "r"((uint32_t)(sa)), "r"((uint32_t)(cnt)) : "memory")
#define MBARRIER_ARRIVE(sa) \
    asm volatile("mbarrier.arrive.shared.b64 _, [%0];" :: "r"((uint32_t)(sa)) : "memory")
#define MBAR_WAIT(sa, ph) do { \
    asm volatile("{\n\t.reg .pred P1;\n\tWL%=:\n\t" \
        "mbarrier.try_wait.parity.acquire.cta.shared::cta.b64 P1, [%0], %1, 0x989680;\n\t" \
        "@P1 bra.uni WD%=;\n\tbra.uni WL%=;\n\tWD%=:\n\t}" \
        :: "r"((uint32_t)(sa)), "r"((uint32_t)(ph)) : "memory"); \
} while (0)
#define FENCE_PROXY_ASYNC() asm volatile("fence.proxy.async;" ::: "memory")

__device__ __forceinline__ void tma_issue(uint32_t dst, const void* src, uint32_t bytes, uint32_t mbar) {
    asm volatile("mbarrier.arrive.expect_tx.shared.b64 _, [%0], %1;"
                 :: "r"(mbar), "r"(bytes) : "memory");
    asm volatile("cp.async.bulk.shared::cta.global.mbarrier::complete_tx::bytes [%0], [%1], %2, [%3];"
                 :: "r"(dst), "l"(src), "r"(bytes), "r"(mbar) : "memory");
}
__device__ __forceinline__ void ldsm4(uint32_t& a, uint32_t& b, uint32_t& c, uint32_t& d, uint32_t addr) {
    asm volatile("ldmatrix.sync.aligned.m8n8.x4.shared.b16 {%0,%1,%2,%3}, [%4];"
                 : "=r"(a), "=r"(b), "=r"(c), "=r"(d) : "r"(addr));
}
__device__ __forceinline__ void mma16816(float* c, uint32_t a0, uint32_t a1, uint32_t a2, uint32_t a3,
                                         uint32_t b0, uint32_t b1) {
    asm volatile("mma.sync.aligned.m16n8k16.row.col.f32.f16.f16.f32 "
                 "{%0,%1,%2,%3}, {%4,%5,%6,%7}, {%8,%9}, {%0,%1,%2,%3};"
                 : "+f"(c[0]), "+f"(c[1]), "+f"(c[2]), "+f"(c[3])
                 : "r"(a0), "r"(a1), "r"(a2), "r"(a3), "r"(b0), "r"(b1));
}
#define BAR_COMPUTE() asm volatile("bar.sync 1, 256;" ::: "memory")

// ---------------- activations ----------------
__device__ __forceinline__ float sigm(float x) { return __fdividef(1.f, 1.f + __expf(-x)); }
__device__ __forceinline__ float tanh_(float x) {
    x = fminf(fmaxf(x, -15.f), 15.f);
    float e = __expf(2.f * x);
    return __fdividef(e - 1.f, e + 1.f);
}

// ---------------- chunk GEMM: 2-term fp16-split, warp tile M32xN32, K-split ----------------
// A tile [64 rows x K] fp16 at Abase, rows RS bytes, 16B-chunk swizzle.
// W rows WR bytes (base offset to this warp's N=32 slab). Warp covers s in [s0, s0+NKH).
template<int RS, int WR, int NKH>
__device__ __forceinline__ void compute_chunk(uint32_t Abase, uint32_t Whi, uint32_t Wlo,
                                              int kw0, int s0, float (&acc)[2][4][4],
                                              int lane, int m0) {
    const int rA = m0 + (lane & 15);
    const int kA = lane >> 4;
    const int xr = lane & 7;
    const int cB = (lane & 7) + ((lane & 16) >> 1);
    const int kB = (lane >> 3) & 1;
    const uint32_t dlo = Wlo - Whi;
#pragma unroll
    for (int si = 0; si < NKH; si++) {
        const int s = s0 + si;
        const int kcA = s * 2;
        uint32_t aaddr = Abase + rA * RS + (((kcA + kA) ^ xr) << 4);
        uint32_t a0[4], a1[4];
        ldsm4(a0[0], a0[1], a0[2], a0[3], aaddr);
        ldsm4(a1[0], a1[1], a1[2], a1[3], aaddr + 16 * RS);
        const int kcW = kw0 + s * 2;
        uint32_t b01 = Whi + cB * WR + (((kcW + kB) ^ xr) << 4);
        uint32_t bh[8], bl[8];
        ldsm4(bh[0], bh[1], bh[2], bh[3], b01);
        ldsm4(bh[4], bh[5], bh[6], bh[7], b01 + 16 * WR);
        ldsm4(bl[0], bl[1], bl[2], bl[3], b01 + dlo);
        ldsm4(bl[4], bl[5], bl[6], bl[7], b01 + dlo + 16 * WR);
#pragma unroll
        for (int ti = 0; ti < 4; ti++) {
            mma16816(acc[0][ti], a0[0], a0[1], a0[2], a0[3], bh[2 * ti], bh[2 * ti + 1]);
            mma16816(acc[0][ti], a0[0], a0[1], a0[2], a0[3], bl[2 * ti], bl[2 * ti + 1]);
            mma16816(acc[1][ti], a1[0], a1[1], a1[2], a1[3], bh[2 * ti], bh[2 * ti + 1]);
            mma16816(acc[1][ti], a1[0], a1[1], a1[2], a1[3], bl[2 * ti], bl[2 * ti + 1]);
        }
    }
}

// ---------------- init: zero h buf0, reset counters, x -> fp16 tile layout ----------------
__global__ void init_kernel(const float* __restrict__ x) {
    int idx = blockIdx.x * blockDim.x + threadIdx.x;
    int stride = gridDim.x * blockDim.x;
    uint32_t* hz = reinterpret_cast<uint32_t*>(&g_hblk[0][0][0][0]);
    for (int i = idx; i < 4 * 4 * 16384 / 4; i += stride) hz[i] = 0u;
    for (int i = idx; i < Bb * Tt * Ii; i += stride) {
        int ii = i & 63;
        int t  = (i >> 6) & 511;
        int b  = i >> 15;
        int grp = b >> 6, m = b & 63;
        unsigned off = (unsigned)m * 128u + ((((unsigned)ii >> 3) ^ (m & 7)) << 4) + (ii & 7) * 2u;
        *reinterpret_cast<__half*>(&g_xblk[t][grp][off]) = __float2half(x[i]);
    }
    if (idx < 16) g_cnt[idx >> 2][idx & 3][0] = 0u;
}

// ---------------- persistent LSTM: warp-specialized, fp16 2-term, K-split warps ----------------
__global__ void __launch_bounds__(NTHR, 1) lstm_kernel(
    const float* __restrict__ W_ih,   // [2048, 64]
    const float* __restrict__ W_hh,   // [2048, 512]
    const float* __restrict__ b_ih,
    const float* __restrict__ b_hh)
{
    extern __shared__ char dsm[];
    // mbarriers: 0=f0 1=f1 2=fx 3=e0 4=e1 5=ex
    __shared__ __align__(8) unsigned long long s_mbar[6];
    __shared__ float s_bias[64];

    const int tid  = threadIdx.x;
    const int lane = tid & 31;
    const int wid  = tid >> 5;
    const int grp  = blockIdx.x >> 5;       // owns 64 batch rows
    const int nc   = blockIdx.x & 31;       // gate cols [nc*64, nc*64+64) -> 16 units

    uint32_t raw = smem_u32(dsm);
    uint32_t base = (raw + 1023u) & ~1023u;
    char* bptr = dsm + (base - raw);

    // ---- stage W slices (once), fp16 split hi/lo, swizzled ----
    for (int idx = tid; idx < 64 * Hh; idx += NTHR) {
        int c = idx >> 9, k = idx & 511;
        int row = (c & 3) * Hh + nc * 16 + (c >> 2);
        float w = W_hh[(size_t)row * Hh + k];
        __half hi = __float2half(w);
        __half lo = __float2half(w - __half2float(hi));
        unsigned off = (unsigned)c * 1024u + ((((unsigned)k >> 3) ^ (c & 7)) << 4) + (k & 7) * 2u;
        *reinterpret_cast<__half*>(bptr + OFF_WHHI + off) = hi;
        *reinterpret_cast<__half*>(bptr + OFF_WHLO + off) = lo;
    }
    for (int idx = tid; idx < 64 * Ii; idx += NTHR) {
        int c = idx >> 6, k = idx & 63;
        int row = (c & 3) * Hh + nc * 16 + (c >> 2);
        float w = W_ih[(size_t)row * Ii + k];
        __half hi = __float2half(w);
        __half lo = __float2half(w - __half2float(hi));
        unsigned off = (unsigned)c * 128u + ((((unsigned)k >> 3) ^ (c & 7)) << 4) + (k & 7) * 2u;
        *reinterpret_cast<__half*>(bptr + OFF_WXHI + off) = hi;
        *reinterpret_cast<__half*>(bptr + OFF_WXLO + off) = lo;
    }
    if (tid < 64) {
        int row = (tid & 3) * Hh + nc * 16 + (tid >> 2);
        s_bias[tid] = b_ih[row] + b_hh[row];
    }
    if (tid == 0) {
        MBARRIER_INIT(smem_u32(&s_mbar[0]), 1);   // full A0 (expect_tx)
        MBARRIER_INIT(smem_u32(&s_mbar[1]), 1);   // full A1
        MBARRIER_INIT(smem_u32(&s_mbar[2]), 1);   // full X
        MBARRIER_INIT(smem_u32(&s_mbar[3]), 8);   // empty A0 (8 compute warps)
        MBARRIER_INIT(smem_u32(&s_mbar[4]), 8);   // empty A1
        MBARRIER_INIT(smem_u32(&s_mbar[5]), 8);   // empty X
    }
    __syncthreads();

    const uint32_t f0 = smem_u32(&s_mbar[0]), f1 = smem_u32(&s_mbar[1]), fx = smem_u32(&s_mbar[2]);
    const uint32_t e0 = smem_u32(&s_mbar[3]), e1 = smem_u32(&s_mbar[4]), ex = smem_u32(&s_mbar[5]);
    const uint32_t Abuf[2] = { base + OFF_A0, base + OFF_A1 };
    const uint32_t XB = base + OFF_XB;

    // =========================== DMA warp ===========================
    if (wid == 8) {
        if (lane == 0) {
            volatile unsigned* cnt[4] = { &g_cnt[grp][0][0], &g_cnt[grp][1][0],
                                          &g_cnt[grp][2][0], &g_cnt[grp][3][0] };
            int pe0 = 1, pe1 = 1, pex = 1;
#pragma unroll 1
            for (int t = 0; t < Tt; t++) {
                const unsigned char (*hsrc)[16384] = g_hblk[t & 1][grp];
                const unsigned target = (unsigned)t * 8u;
                // x tile (no producer dependency)
                MBAR_WAIT(ex, pex); pex ^= 1;
                FENCE_PROXY_ASYNC();
                tma_issue(XB, &g_xblk[t][grp][0], 8192, fx);
                // h chunks 0..3, ring A0/A1
#pragma unroll
                for (int kc = 0; kc < 4; kc++) {
                    if (kc & 1) { MBAR_WAIT(e1, pe1); pe1 ^= 1; }
                    else        { MBAR_WAIT(e0, pe0); pe0 ^= 1; }
                    unsigned v;
                    while (true) {
                        asm volatile("ld.acquire.gpu.global.u32 %0, [%1];" : "=r"(v) : "l"(cnt[kc]));
                        if (v >= target) break;
                        asm volatile("nanosleep.u32 32;");
                    }
                    FENCE_PROXY_ASYNC();
                    tma_issue(Abuf[kc & 1], &hsrc[kc][0], 16384, (kc & 1) ? f1 : f0);
                }
            }
        }
        return;
    }

    // =========================== compute warps ===========================
    // warp decomposition: mh = M half (32 rows), nh = N half (32 cols), ks = K split
    const int mh = wid & 1, nh = (wid >> 1) & 1, ks = wid >> 2;
    const int m0 = mh * 32;
    const int n0 = nh * 32;
    const uint32_t WhHiW = base + OFF_WHHI + n0 * 1024;
    const uint32_t WhLoW = base + OFF_WHLO + n0 * 1024;
    const uint32_t WxHiW = base + OFF_WXHI + n0 * 128;
    const uint32_t WxLoW = base + OFF_WXLO + n0 * 128;
    // epilogue scratch: two planes [64][68] floats, spans A0+A1+XB (34.8KB < 40KB)
    float* scr = reinterpret_cast<float*>(bptr + OFF_A0);
    float* myplane = scr + ks * (64 * 68);

    const int em = tid & 63, eg = tid >> 6;  // epilogue mapping over 256 threads
    float bia[16];
#pragma unroll
    for (int q = 0; q < 16; q++) bia[q] = s_bias[eg * 16 + q];

    const int u0 = nc * 16 + eg * 4;
    const int kcb = u0 >> 7, ucol = u0 & 127;
    const unsigned hoff = (unsigned)em * 256u + ((((unsigned)ucol >> 3) ^ (em & 7)) << 4) + (ucol & 7) * 2u;
    unsigned* mycnt = &g_cnt[grp][nc >> 3][0];

    float cs[4] = {0.f, 0.f, 0.f, 0.f};
    int pf0 = 0, pf1 = 0, pfx = 0;

#pragma unroll 1
    for (int t = 0; t < Tt; t++) {
        const int wb = (t & 1) ^ 1;

        float acc[2][4][4];
#pragma unroll
        for (int m = 0; m < 2; m++)
#pragma unroll
            for (int a = 0; a < 4; a++)
#pragma unroll
                for (int bq = 0; bq < 4; bq++) acc[m][a][bq] = 0.f;

        // chunk 0 (A0)
        MBAR_WAIT(f0, pf0); pf0 ^= 1;
        compute_chunk<256, 1024, 4>(Abuf[0], WhHiW, WhLoW, 0, ks * 4, acc, lane, m0);
        if (lane == 0) MBARRIER_ARRIVE(e0);
        // chunk 1 (A1)
        MBAR_WAIT(f1, pf1); pf1 ^= 1;
        compute_chunk<256, 1024, 4>(Abuf[1], WhHiW, WhLoW, 16, ks * 4, acc, lane, m0);
        if (lane == 0) MBARRIER_ARRIVE(e1);
        // chunk 2 (A0) — empty arrival deferred to post-epilogue (scratch aliases A0)
        MBAR_WAIT(f0, pf0); pf0 ^= 1;
        compute_chunk<256, 1024, 4>(Abuf[0], WhHiW, WhLoW, 32, ks * 4, acc, lane, m0);
        // chunk 3 (A1) — deferred (scratch spans A1)
        MBAR_WAIT(f1, pf1); pf1 ^= 1;
        compute_chunk<256, 1024, 4>(Abuf[1], WhHiW, WhLoW, 48, ks * 4, acc, lane, m0);
        // x chunk — deferred (scratch spans XB)
        MBAR_WAIT(fx, pfx); pfx ^= 1;
        compute_chunk<128, 128, 2>(XB, WxHiW, WxLoW, 0, ks * 2, acc, lane, m0);

        // ---- epilogue ----
        BAR_COMPUTE();     // all warps done reading A0/A1/XB before scratch overwrite
        {
            const int r0 = m0 + (lane >> 2), cb = n0 + (lane & 3) * 2;
#pragma unroll
            for (int m = 0; m < 2; m++)
#pragma unroll
                for (int ti = 0; ti < 4; ti++) {
                    *reinterpret_cast<float2*>(&myplane[(r0 + m * 16) * 68 + ti * 8 + cb]) =
                        make_float2(acc[m][ti][0], acc[m][ti][1]);
                    *reinterpret_cast<float2*>(&myplane[(r0 + 8 + m * 16) * 68 + ti * 8 + cb]) =
                        make_float2(acc[m][ti][2], acc[m][ti][3]);
                }
        }
        BAR_COMPUTE();
        {
            __align__(8) __half hh[4];
            float hv4[4];
#pragma unroll
            for (int q = 0; q < 4; q++) {
                float4 v  = *reinterpret_cast<float4*>(&scr[em * 68 + eg * 16 + q * 4]);
                float4 v2 = *reinterpret_cast<float4*>(&scr[64 * 68 + em * 68 + eg * 16 + q * 4]);
                float iv = sigm(v.x + v2.x + bia[q * 4 + 0]);
                float fv = sigm(v.y + v2.y + bia[q * 4 + 1]);
                float gv = tanh_(v.z + v2.z + bia[q * 4 + 2]);
                float ov = sigm(v.w + v2.w + bia[q * 4 + 3]);
                cs[q] = fv * cs[q] + iv * gv;
                float hv = ov * tanh_(cs[q]);
                hv4[q] = hv;
                hh[q] = __float2half(hv);
            }
            unsigned char* dst = &g_hblk[wb][grp][kcb][0] + hoff;
            *reinterpret_cast<uint2*>(dst) = *reinterpret_cast<uint2*>(hh);
            if (t == Tt - 1)
                *reinterpret_cast<float4*>(&g_hfinal[grp * 64 + em][u0]) =
                    make_float4(hv4[0], hv4[1], hv4[2], hv4[3]);
        }
        BAR_COMPUTE();     // all h writes + all scratch reads done
        if (tid == 0 && t < Tt - 1)
            asm volatile("red.release.gpu.global.add.u32 [%0], %1;" :: "l"(mycnt), "r"(1u) : "memory");
        if (lane == 0) { MBARRIER_ARRIVE(e0); MBARRIER_ARRIVE(e1); MBARRIER_ARRIVE(ex); }
    }
}

// ---------------- final FC ----------------
__global__ void fc_kernel(const float* __restrict__ W_fc,
                          const float* __restrict__ b_fc,
                          float* __restrict__ out) {
    int b = threadIdx.x;
    float s = 0.f;
#pragma unroll 8
    for (int k = 0; k < Hh; k++) s += g_hfinal[b][k] * W_fc[k];
    out[b] = s + b_fc[0];
}

extern "C" void kernel_launch(void* const* d_in, const int* in_sizes, int n_in,
                              void* d_out, int out_size) {
    const float* x    = (const float*)d_in[0];
    const float* W_ih = (const float*)d_in[1];
    const float* W_hh = (const float*)d_in[2];
    const float* b_ih = (const float*)d_in[3];
    const float* b_hh = (const float*)d_in[4];
    const float* W_fc = (const float*)d_in[5];
    const float* b_fc = (const float*)d_in[6];
    float* out = (float*)d_out;

    cudaFuncSetAttribute(lstm_kernel, cudaFuncAttributeMaxDynamicSharedMemorySize, DSM_BYTES);

    init_kernel<<<1024, 256>>>(x);
    lstm_kernel<<<128, NTHR, DSM_BYTES>>>(W_ih, W_hh, b_ih, b_hh);
    fc_kernel<<<1, Bb>>>(W_fc, b_fc, out);
}

// round 10
// speedup vs baseline: 1.0629x; 1.0629x over previous
#include <cuda_runtime.h>
#include <cuda_fp16.h>
#include <cstdint>

// ---------------- problem constants ----------------
#define Bb   256
#define Tt   512
#define Ii   64
#define Hh   512
#define NTHR 288     // 8 compute warps (2M x 2N x 2Ksplit, tile M32xN32) + 1 DMA warp

// SMEM layout offsets (from 1024-aligned base)
#define OFF_WHHI 0            // W_hh slice (fp16, 1-term): [64 c][1024 B] = 64KB
#define OFF_WXHI 65536        // W_ih slice: [64 c][128 B] = 8KB
#define OFF_A0   73728        // h chunk buf 0: 16KB (fp16)
#define OFF_A1   90112        // contiguous with A0
#define OFF_XB   106496       // x buf: 8KB (epi scratch spans A0+A1+XB = 40KB)
#define DSM_BYTES (114688 + 1024)

// ---------------- persistent device state ----------------
// h tile layout: [buf][group][kchunk][16KB]; group = half*2 + mtile (64 batch rows)
// chunk = 64 rows x 128 units fp16 (256B/row), 16B-chunk swizzle
__device__ __align__(1024) unsigned char g_hblk[2][4][4][16384];
// x tile layout: [t][group][8KB] = 64 rows x 64 fp16 (128B/row), swizzled
__device__ __align__(1024) unsigned char g_xblk[Tt][4][8192];
__device__ float    g_hfinal[Bb][Hh];
__device__ unsigned g_cnt[4][4][16];   // [group][kchunk], padded to 64B

// ---------------- PTX helpers ----------------
__device__ __forceinline__ uint32_t smem_u32(const void* p) {
    uint32_t a;
    asm("{ .reg .u64 t; cvta.to.shared.u64 t, %1; cvt.u32.u64 %0, t; }" : "=r"(a) : "l"(p));
    return a;
}
#define MBARRIER_INIT(sa, cnt) \
    asm volatile("mbarrier.init.shared.b64 [%0], %1;" :: "r"((uint32_t)(sa)), "r"((uint32_t)(cnt)) : "memory")
#define MBARRIER_ARRIVE(sa) \
    asm volatile("mbarrier.arrive.shared.b64 _, [%0];" :: "r"((uint32_t)(sa)) : "memory")
#define MBAR_WAIT(sa, ph) do { \
    asm volatile("{\n\t.reg .pred P1;\n\tWL%=:\n\t" \
        "mbarrier.try_wait.parity.acquire.cta.shared::cta.b64 P1, [%0], %1, 0x989680;\n\t" \
        "@P1 bra.uni WD%=;\n\tbra.uni WL%=;\n\tWD%=:\n\t}" \
        :: "r"((uint32_t)(sa)), "r"((uint32_t)(ph)) : "memory"); \
} while (0)
#define FENCE_PROXY_ASYNC() asm volatile("fence.proxy.async;" ::: "memory")

__device__ __forceinline__ void tma_issue(uint32_t dst, const void* src, uint32_t bytes, uint32_t mbar) {
    asm volatile("mbarrier.arrive.expect_tx.shared.b64 _, [%0], %1;"
                 :: "r"(mbar), "r"(bytes) : "memory");
    asm volatile("cp.async.bulk.shared::cta.global.mbarrier::complete_tx::bytes [%0], [%1], %2, [%3];"
                 :: "r"(dst), "l"(src), "r"(bytes), "r"(mbar) : "memory");
}
__device__ __forceinline__ void ldsm4(uint32_t& a, uint32_t& b, uint32_t& c, uint32_t& d, uint32_t addr) {
    asm volatile("ldmatrix.sync.aligned.m8n8.x4.shared.b16 {%0,%1,%2,%3}, [%4];"
                 : "=r"(a), "=r"(b), "=r"(c), "=r"(d) : "r"(addr));
}
__device__ __forceinline__ void mma16816(float* c, uint32_t a0, uint32_t a1, uint32_t a2, uint32_t a3,
                                         uint32_t b0, uint32_t b1) {
    asm volatile("mma.sync.aligned.m16n8k16.row.col.f32.f16.f16.f32 "
                 "{%0,%1,%2,%3}, {%4,%5,%6,%7}, {%8,%9}, {%0,%1,%2,%3};"
                 : "+f"(c[0]), "+f"(c[1]), "+f"(c[2]), "+f"(c[3])
                 : "r"(a0), "r"(a1), "r"(a2), "r"(a3), "r"(b0), "r"(b1));
}
#define BAR_COMPUTE() asm volatile("bar.sync 1, 256;" ::: "memory")

// ---------------- activations ----------------
__device__ __forceinline__ float sigm(float x) { return __fdividef(1.f, 1.f + __expf(-x)); }
__device__ __forceinline__ float tanh_(float x) {
    x = fminf(fmaxf(x, -15.f), 15.f);
    float e = __expf(2.f * x);
    return __fdividef(e - 1.f, e + 1.f);
}

// ---------------- chunk GEMM: 1-term fp16, warp tile M32xN32, K-split ----------------
// A tile [64 rows x K] fp16 at Abase, rows RS bytes, 16B-chunk swizzle.
// W rows WR bytes (base offset to this warp's N=32 slab). Warp covers s in [s0, s0+NKH).
template<int RS, int WR, int NKH>
__device__ __forceinline__ void compute_chunk(uint32_t Abase, uint32_t Whi,
                                              int kw0, int s0, float (&acc)[2][4][4],
                                              int lane, int m0) {
    const int rA = m0 + (lane & 15);
    const int kA = lane >> 4;
    const int xr = lane & 7;
    const int cB = (lane & 7) + ((lane & 16) >> 1);
    const int kB = (lane >> 3) & 1;
#pragma unroll
    for (int si = 0; si < NKH; si++) {
        const int s = s0 + si;
        const int kcA = s * 2;
        uint32_t aaddr = Abase + rA * RS + (((kcA + kA) ^ xr) << 4);
        uint32_t a0[4], a1[4];
        ldsm4(a0[0], a0[1], a0[2], a0[3], aaddr);
        ldsm4(a1[0], a1[1], a1[2], a1[3], aaddr + 16 * RS);
        const int kcW = kw0 + s * 2;
        uint32_t b01 = Whi + cB * WR + (((kcW + kB) ^ xr) << 4);
        uint32_t bh[8];
        ldsm4(bh[0], bh[1], bh[2], bh[3], b01);
        ldsm4(bh[4], bh[5], bh[6], bh[7], b01 + 16 * WR);
#pragma unroll
        for (int ti = 0; ti < 4; ti++) {
            mma16816(acc[0][ti], a0[0], a0[1], a0[2], a0[3], bh[2 * ti], bh[2 * ti + 1]);
            mma16816(acc[1][ti], a1[0], a1[1], a1[2], a1[3], bh[2 * ti], bh[2 * ti + 1]);
        }
    }
}

// ---------------- init: zero h buf0, reset counters, x -> fp16 tile layout ----------------
__global__ void init_kernel(const float* __restrict__ x) {
    int idx = blockIdx.x * blockDim.x + threadIdx.x;
    int stride = gridDim.x * blockDim.x;
    uint32_t* hz = reinterpret_cast<uint32_t*>(&g_hblk[0][0][0][0]);
    for (int i = idx; i < 4 * 4 * 16384 / 4; i += stride) hz[i] = 0u;
    for (int i = idx; i < Bb * Tt * Ii; i += stride) {
        int ii = i & 63;
        int t  = (i >> 6) & 511;
        int b  = i >> 15;
        int grp = b >> 6, m = b & 63;
        unsigned off = (unsigned)m * 128u + ((((unsigned)ii >> 3) ^ (m & 7)) << 4) + (ii & 7) * 2u;
        *reinterpret_cast<__half*>(&g_xblk[t][grp][off]) = __float2half(x[i]);
    }
    if (idx < 16) g_cnt[idx >> 2][idx & 3][0] = 0u;
}

// ---------------- persistent LSTM: warp-specialized, fp16 1-term W ----------------
__global__ void __launch_bounds__(NTHR, 1) lstm_kernel(
    const float* __restrict__ W_ih,   // [2048, 64]
    const float* __restrict__ W_hh,   // [2048, 512]
    const float* __restrict__ b_ih,
    const float* __restrict__ b_hh)
{
    extern __shared__ char dsm[];
    // mbarriers: 0=f0 1=f1 2=fx 3=e0 4=e1 5=ex
    __shared__ __align__(8) unsigned long long s_mbar[6];
    __shared__ float s_bias[64];

    const int tid  = threadIdx.x;
    const int lane = tid & 31;
    const int wid  = tid >> 5;
    const int grp  = blockIdx.x >> 5;       // owns 64 batch rows
    const int nc   = blockIdx.x & 31;       // gate cols [nc*64, nc*64+64) -> 16 units

    uint32_t raw = smem_u32(dsm);
    uint32_t base = (raw + 1023u) & ~1023u;
    char* bptr = dsm + (base - raw);

    // ---- stage W slices (once), fp16, swizzled ----
    for (int idx = tid; idx < 64 * Hh; idx += NTHR) {
        int c = idx >> 9, k = idx & 511;
        int row = (c & 3) * Hh + nc * 16 + (c >> 2);
        float w = W_hh[(size_t)row * Hh + k];
        unsigned off = (unsigned)c * 1024u + ((((unsigned)k >> 3) ^ (c & 7)) << 4) + (k & 7) * 2u;
        *reinterpret_cast<__half*>(bptr + OFF_WHHI + off) = __float2half(w);
    }
    for (int idx = tid; idx < 64 * Ii; idx += NTHR) {
        int c = idx >> 6, k = idx & 63;
        int row = (c & 3) * Hh + nc * 16 + (c >> 2);
        float w = W_ih[(size_t)row * Ii + k];
        unsigned off = (unsigned)c * 128u + ((((unsigned)k >> 3) ^ (c & 7)) << 4) + (k & 7) * 2u;
        *reinterpret_cast<__half*>(bptr + OFF_WXHI + off) = __float2half(w);
    }
    if (tid < 64) {
        int row = (tid & 3) * Hh + nc * 16 + (tid >> 2);
        s_bias[tid] = b_ih[row] + b_hh[row];
    }
    if (tid == 0) {
        MBARRIER_INIT(smem_u32(&s_mbar[0]), 1);   // full A0 (expect_tx)
        MBARRIER_INIT(smem_u32(&s_mbar[1]), 1);   // full A1
        MBARRIER_INIT(smem_u32(&s_mbar[2]), 1);   // full X
        MBARRIER_INIT(smem_u32(&s_mbar[3]), 8);   // empty A0 (8 compute warps)
        MBARRIER_INIT(smem_u32(&s_mbar[4]), 8);   // empty A1
        MBARRIER_INIT(smem_u32(&s_mbar[5]), 8);   // empty X
    }
    __syncthreads();

    const uint32_t f0 = smem_u32(&s_mbar[0]), f1 = smem_u32(&s_mbar[1]), fx = smem_u32(&s_mbar[2]);
    const uint32_t e0 = smem_u32(&s_mbar[3]), e1 = smem_u32(&s_mbar[4]), ex = smem_u32(&s_mbar[5]);
    const uint32_t Abuf[2] = { base + OFF_A0, base + OFF_A1 };
    const uint32_t XB = base + OFF_XB;

    // =========================== DMA warp ===========================
    if (wid == 8) {
        if (lane == 0) {
            volatile unsigned* cnt[4] = { &g_cnt[grp][0][0], &g_cnt[grp][1][0],
                                          &g_cnt[grp][2][0], &g_cnt[grp][3][0] };
            int pe0 = 1, pe1 = 1, pex = 1;
#pragma unroll 1
            for (int t = 0; t < Tt; t++) {
                const unsigned char (*hsrc)[16384] = g_hblk[t & 1][grp];
                const unsigned target = (unsigned)t * 8u;
                // x tile (no producer dependency)
                MBAR_WAIT(ex, pex); pex ^= 1;
                FENCE_PROXY_ASYNC();
                tma_issue(XB, &g_xblk[t][grp][0], 8192, fx);
                // h chunks 0..3, ring A0/A1
#pragma unroll
                for (int kc = 0; kc < 4; kc++) {
                    if (kc & 1) { MBAR_WAIT(e1, pe1); pe1 ^= 1; }
                    else        { MBAR_WAIT(e0, pe0); pe0 ^= 1; }
                    unsigned v;
                    while (true) {
                        asm volatile("ld.acquire.gpu.global.u32 %0, [%1];" : "=r"(v) : "l"(cnt[kc]));
                        if (v >= target) break;
                        asm volatile("nanosleep.u32 32;");
                    }
                    FENCE_PROXY_ASYNC();
                    tma_issue(Abuf[kc & 1], &hsrc[kc][0], 16384, (kc & 1) ? f1 : f0);
                }
            }
        }
        return;
    }

    // =========================== compute warps ===========================
    // warp decomposition: mh = M half (32 rows), nh = N half (32 cols), ks = K split
    const int mh = wid & 1, nh = (wid >> 1) & 1, ks = wid >> 2;
    const int m0 = mh * 32;
    const int n0 = nh * 32;
    const uint32_t WhW = base + OFF_WHHI + n0 * 1024;
    const uint32_t WxW = base + OFF_WXHI + n0 * 128;
    // epilogue scratch: two planes [64][68] floats, spans A0+A1+XB (34.8KB < 40KB)
    float* scr = reinterpret_cast<float*>(bptr + OFF_A0);
    float* myplane = scr + ks * (64 * 68);

    const int em = tid & 63, eg = tid >> 6;  // epilogue mapping over 256 threads
    float bia[16];
#pragma unroll
    for (int q = 0; q < 16; q++) bia[q] = s_bias[eg * 16 + q];

    const int u0 = nc * 16 + eg * 4;
    const int kcb = u0 >> 7, ucol = u0 & 127;
    const unsigned hoff = (unsigned)em * 256u + ((((unsigned)ucol >> 3) ^ (em & 7)) << 4) + (ucol & 7) * 2u;
    unsigned* mycnt = &g_cnt[grp][nc >> 3][0];

    float cs[4] = {0.f, 0.f, 0.f, 0.f};
    int pf0 = 0, pf1 = 0, pfx = 0;

#pragma unroll 1
    for (int t = 0; t < Tt; t++) {
        const int wb = (t & 1) ^ 1;

        float acc[2][4][4];
#pragma unroll
        for (int m = 0; m < 2; m++)
#pragma unroll
            for (int a = 0; a < 4; a++)
#pragma unroll
                for (int bq = 0; bq < 4; bq++) acc[m][a][bq] = 0.f;

        // chunk 0 (A0)
        MBAR_WAIT(f0, pf0); pf0 ^= 1;
        compute_chunk<256, 1024, 4>(Abuf[0], WhW, 0, ks * 4, acc, lane, m0);
        if (lane == 0) MBARRIER_ARRIVE(e0);
        // chunk 1 (A1)
        MBAR_WAIT(f1, pf1); pf1 ^= 1;
        compute_chunk<256, 1024, 4>(Abuf[1], WhW, 16, ks * 4, acc, lane, m0);
        if (lane == 0) MBARRIER_ARRIVE(e1);
        // chunk 2 (A0) — empty arrival deferred to post-epilogue (scratch aliases A0)
        MBAR_WAIT(f0, pf0); pf0 ^= 1;
        compute_chunk<256, 1024, 4>(Abuf[0], WhW, 32, ks * 4, acc, lane, m0);
        // chunk 3 (A1) — deferred (scratch spans A1)
        MBAR_WAIT(f1, pf1); pf1 ^= 1;
        compute_chunk<256, 1024, 4>(Abuf[1], WhW, 48, ks * 4, acc, lane, m0);
        // x chunk — deferred (scratch spans XB)
        MBAR_WAIT(fx, pfx); pfx ^= 1;
        compute_chunk<128, 128, 2>(XB, WxW, 0, ks * 2, acc, lane, m0);

        // ---- epilogue ----
        BAR_COMPUTE();     // all warps done reading A0/A1/XB before scratch overwrite
        {
            const int r0 = m0 + (lane >> 2), cb = n0 + (lane & 3) * 2;
#pragma unroll
            for (int m = 0; m < 2; m++)
#pragma unroll
                for (int ti = 0; ti < 4; ti++) {
                    *reinterpret_cast<float2*>(&myplane[(r0 + m * 16) * 68 + ti * 8 + cb]) =
                        make_float2(acc[m][ti][0], acc[m][ti][1]);
                    *reinterpret_cast<float2*>(&myplane[(r0 + 8 + m * 16) * 68 + ti * 8 + cb]) =
                        make_float2(acc[m][ti][2], acc[m][ti][3]);
                }
        }
        BAR_COMPUTE();
        {
            __align__(8) __half hh[4];
            float hv4[4];
#pragma unroll
            for (int q = 0; q < 4; q++) {
                float4 v  = *reinterpret_cast<float4*>(&scr[em * 68 + eg * 16 + q * 4]);
                float4 v2 = *reinterpret_cast<float4*>(&scr[64 * 68 + em * 68 + eg * 16 + q * 4]);
                float iv = sigm(v.x + v2.x + bia[q * 4 + 0]);
                float fv = sigm(v.y + v2.y + bia[q * 4 + 1]);
                float gv = tanh_(v.z + v2.z + bia[q * 4 + 2]);
                float ov = sigm(v.w + v2.w + bia[q * 4 + 3]);
                cs[q] = fv * cs[q] + iv * gv;
                float hv = ov * tanh_(cs[q]);
                hv4[q] = hv;
                hh[q] = __float2half(hv);
            }
            unsigned char* dst = &g_hblk[wb][grp][kcb][0] + hoff;
            *reinterpret_cast<uint2*>(dst) = *reinterpret_cast<uint2*>(hh);
            if (t == Tt - 1)
                *reinterpret_cast<float4*>(&g_hfinal[grp * 64 + em][u0]) =
                    make_float4(hv4[0], hv4[1], hv4[2], hv4[3]);
        }
        BAR_COMPUTE();     // all h writes + all scratch reads done
        if (tid == 0 && t < Tt - 1)
            asm volatile("red.release.gpu.global.add.u32 [%0], %1;" :: "l"(mycnt), "r"(1u) : "memory");
        if (lane == 0) { MBARRIER_ARRIVE(e0); MBARRIER_ARRIVE(e1); MBARRIER_ARRIVE(ex); }
    }
}

// ---------------- final FC ----------------
__global__ void fc_kernel(const float* __restrict__ W_fc,
                          const float* __restrict__ b_fc,
                          float* __restrict__ out) {
    int b = threadIdx.x;
    float s = 0.f;
#pragma unroll 8
    for (int k = 0; k < Hh; k++) s += g_hfinal[b][k] * W_fc[k];
    out[b] = s + b_fc[0];
}

extern "C" void kernel_launch(void* const* d_in, const int* in_sizes, int n_in,
                              void* d_out, int out_size) {
    const float* x    = (const float*)d_in[0];
    const float* W_ih = (const float*)d_in[1];
    const float* W_hh = (const float*)d_in[2];
    const float* b_ih = (const float*)d_in[3];
    const float* b_hh = (const float*)d_in[4];
    const float* W_fc = (const float*)d_in[5];
    const float* b_fc = (const float*)d_in[6];
    float* out = (float*)d_out;

    cudaFuncSetAttribute(lstm_kernel, cudaFuncAttributeMaxDynamicSharedMemorySize, DSM_BYTES);

    init_kernel<<<1024, 256>>>(x);
    lstm_kernel<<<128, NTHR, DSM_BYTES>>>(W_ih, W_hh, b_ih, b_hh);
    fc_kernel<<<1, Bb>>>(W_fc, b_fc, out);
}

// round 11
// speedup vs baseline: 1.1357x; 1.0684x over previous
#include <cuda_runtime.h>
#include <cuda_fp16.h>
#include <cstdint>

// ---------------- problem constants ----------------
#define Bb   256
#define Tt   512
#define Ii   64
#define Hh   512
#define NTHR 288     // 8 compute warps (2M x 2N x 2Ksplit, tile M32xN32) + 1 DMA warp

// SMEM layout offsets (from 1024-aligned base)
#define OFF_WH   0            // W_hh slice (fp16): [64 c][1024 B] = 64KB
#define OFF_WX   65536        // W_ih slice: [64 c][128 B] = 8KB
#define OFF_A    73728        // 4 h chunk bufs, 16KB each (fp16)
#define OFF_XB   139264       // x buf: 8KB
#define OFF_SCR  147456       // epilogue scratch: 2 planes x 64x68 f32 = 34816 B
#define DSM_BYTES (182272 + 1024)

// ---------------- persistent device state ----------------
// h tile layout: [buf][group][kchunk][16KB]; group = half*2 + mtile (64 batch rows)
// chunk = 64 rows x 128 units fp16 (256B/row), 16B-chunk swizzle
__device__ __align__(1024) unsigned char g_hblk[2][4][4][16384];
// x tile layout: [t][group][8KB] = 64 rows x 64 fp16 (128B/row), swizzled
__device__ __align__(1024) unsigned char g_xblk[Tt][4][8192];
__device__ float    g_hfinal[Bb][Hh];
__device__ unsigned g_cnt[4][4][16];   // [group][kchunk], padded to 64B

// ---------------- PTX helpers ----------------
__device__ __forceinline__ uint32_t smem_u32(const void* p) {
    uint32_t a;
    asm("{ .reg .u64 t; cvta.to.shared.u64 t, %1; cvt.u32.u64 %0, t; }" : "=r"(a) : "l"(p));
    return a;
}
#define MBARRIER_INIT(sa, cnt) \
    asm volatile("mbarrier.init.shared.b64 [%0], %1;" :: "r"((uint32_t)(sa)), "r"((uint32_t)(cnt)) : "memory")
#define MBARRIER_ARRIVE(sa) \
    asm volatile("mbarrier.arrive.shared.b64 _, [%0];" :: "r"((uint32_t)(sa)) : "memory")
#define MBAR_WAIT(sa, ph) do { \
    asm volatile("{\n\t.reg .pred P1;\n\tWL%=:\n\t" \
        "mbarrier.try_wait.parity.acquire.cta.shared::cta.b64 P1, [%0], %1, 0x989680;\n\t" \
        "@P1 bra.uni WD%=;\n\tbra.uni WL%=;\n\tWD%=:\n\t}" \
        :: "r"((uint32_t)(sa)), "r"((uint32_t)(ph)) : "memory"); \
} while (0)
#define FENCE_PROXY_ASYNC() asm volatile("fence.proxy.async;" ::: "memory")

__device__ __forceinline__ void tma_issue(uint32_t dst, const void* src, uint32_t bytes, uint32_t mbar) {
    asm volatile("mbarrier.arrive.expect_tx.shared.b64 _, [%0], %1;"
                 :: "r"(mbar), "r"(bytes) : "memory");
    asm volatile("cp.async.bulk.shared::cta.global.mbarrier::complete_tx::bytes [%0], [%1], %2, [%3];"
                 :: "r"(dst), "l"(src), "r"(bytes), "r"(mbar) : "memory");
}
__device__ __forceinline__ void ldsm4(uint32_t& a, uint32_t& b, uint32_t& c, uint32_t& d, uint32_t addr) {
    asm volatile("ldmatrix.sync.aligned.m8n8.x4.shared.b16 {%0,%1,%2,%3}, [%4];"
                 : "=r"(a), "=r"(b), "=r"(c), "=r"(d) : "r"(addr));
}
__device__ __forceinline__ void mma16816(float* c, uint32_t a0, uint32_t a1, uint32_t a2, uint32_t a3,
                                         uint32_t b0, uint32_t b1) {
    asm volatile("mma.sync.aligned.m16n8k16.row.col.f32.f16.f16.f32 "
                 "{%0,%1,%2,%3}, {%4,%5,%6,%7}, {%8,%9}, {%0,%1,%2,%3};"
                 : "+f"(c[0]), "+f"(c[1]), "+f"(c[2]), "+f"(c[3])
                 : "r"(a0), "r"(a1), "r"(a2), "r"(a3), "r"(b0), "r"(b1));
}
#define BAR_COMPUTE() asm volatile("bar.sync 1, 256;" ::: "memory")

// ---------------- activations ----------------
__device__ __forceinline__ float sigm(float x) { return __fdividef(1.f, 1.f + __expf(-x)); }
__device__ __forceinline__ float tanh_(float x) {
    x = fminf(fmaxf(x, -15.f), 15.f);
    float e = __expf(2.f * x);
    return __fdividef(e - 1.f, e + 1.f);
}

// ---------------- chunk GEMM: 1-term fp16, warp tile M32xN32, K-split ----------------
// A tile [64 rows x K] fp16 at Abase, rows RS bytes, 16B-chunk swizzle.
// W rows WR bytes (base offset to this warp's N=32 slab). Warp covers s in [s0, s0+NKH).
template<int RS, int WR, int NKH>
__device__ __forceinline__ void compute_chunk(uint32_t Abase, uint32_t Whi,
                                              int kw0, int s0, float (&acc)[2][4][4],
                                              int lane, int m0) {
    const int rA = m0 + (lane & 15);
    const int kA = lane >> 4;
    const int xr = lane & 7;
    const int cB = (lane & 7) + ((lane & 16) >> 1);
    const int kB = (lane >> 3) & 1;
#pragma unroll
    for (int si = 0; si < NKH; si++) {
        const int s = s0 + si;
        const int kcA = s * 2;
        uint32_t aaddr = Abase + rA * RS + (((kcA + kA) ^ xr) << 4);
        uint32_t a0[4], a1[4];
        ldsm4(a0[0], a0[1], a0[2], a0[3], aaddr);
        ldsm4(a1[0], a1[1], a1[2], a1[3], aaddr + 16 * RS);
        const int kcW = kw0 + s * 2;
        uint32_t b01 = Whi + cB * WR + (((kcW + kB) ^ xr) << 4);
        uint32_t bh[8];
        ldsm4(bh[0], bh[1], bh[2], bh[3], b01);
        ldsm4(bh[4], bh[5], bh[6], bh[7], b01 + 16 * WR);
#pragma unroll
        for (int ti = 0; ti < 4; ti++) {
            mma16816(acc[0][ti], a0[0], a0[1], a0[2], a0[3], bh[2 * ti], bh[2 * ti + 1]);
            mma16816(acc[1][ti], a1[0], a1[1], a1[2], a1[3], bh[2 * ti], bh[2 * ti + 1]);
        }
    }
}

// ---------------- init: zero h buf0, reset counters, x -> fp16 tile layout ----------------
__global__ void init_kernel(const float* __restrict__ x) {
    int idx = blockIdx.x * blockDim.x + threadIdx.x;
    int stride = gridDim.x * blockDim.x;
    uint32_t* hz = reinterpret_cast<uint32_t*>(&g_hblk[0][0][0][0]);
    for (int i = idx; i < 4 * 4 * 16384 / 4; i += stride) hz[i] = 0u;
    for (int i = idx; i < Bb * Tt * Ii; i += stride) {
        int ii = i & 63;
        int t  = (i >> 6) & 511;
        int b  = i >> 15;
        int grp = b >> 6, m = b & 63;
        unsigned off = (unsigned)m * 128u + ((((unsigned)ii >> 3) ^ (m & 7)) << 4) + (ii & 7) * 2u;
        *reinterpret_cast<__half*>(&g_xblk[t][grp][off]) = __float2half(x[i]);
    }
    if (idx < 16) g_cnt[idx >> 2][idx & 3][0] = 0u;
}

// ---------------- persistent LSTM: warp-specialized, 4-deep TMA, fp16 1-term ----------------
__global__ void __launch_bounds__(NTHR, 1) lstm_kernel(
    const float* __restrict__ W_ih,   // [2048, 64]
    const float* __restrict__ W_hh,   // [2048, 512]
    const float* __restrict__ b_ih,
    const float* __restrict__ b_hh)
{
    extern __shared__ char dsm[];
    // mbarriers: 0..3 = full A[kc], 4 = full X, 5..8 = empty A[kc], 9 = empty X
    __shared__ __align__(8) unsigned long long s_mbar[10];
    __shared__ float s_bias[64];

    const int tid  = threadIdx.x;
    const int lane = tid & 31;
    const int wid  = tid >> 5;
    const int grp  = blockIdx.x >> 5;       // owns 64 batch rows
    const int nc   = blockIdx.x & 31;       // gate cols [nc*64, nc*64+64) -> 16 units

    uint32_t raw = smem_u32(dsm);
    uint32_t base = (raw + 1023u) & ~1023u;
    char* bptr = dsm + (base - raw);

    // ---- stage W slices (once), fp16, swizzled ----
    for (int idx = tid; idx < 64 * Hh; idx += NTHR) {
        int c = idx >> 9, k = idx & 511;
        int row = (c & 3) * Hh + nc * 16 + (c >> 2);
        float w = W_hh[(size_t)row * Hh + k];
        unsigned off = (unsigned)c * 1024u + ((((unsigned)k >> 3) ^ (c & 7)) << 4) + (k & 7) * 2u;
        *reinterpret_cast<__half*>(bptr + OFF_WH + off) = __float2half(w);
    }
    for (int idx = tid; idx < 64 * Ii; idx += NTHR) {
        int c = idx >> 6, k = idx & 63;
        int row = (c & 3) * Hh + nc * 16 + (c >> 2);
        float w = W_ih[(size_t)row * Ii + k];
        unsigned off = (unsigned)c * 128u + ((((unsigned)k >> 3) ^ (c & 7)) << 4) + (k & 7) * 2u;
        *reinterpret_cast<__half*>(bptr + OFF_WX + off) = __float2half(w);
    }
    if (tid < 64) {
        int row = (tid & 3) * Hh + nc * 16 + (tid >> 2);
        s_bias[tid] = b_ih[row] + b_hh[row];
    }
    if (tid == 0) {
#pragma unroll
        for (int i = 0; i < 5; i++) MBARRIER_INIT(smem_u32(&s_mbar[i]), 1);   // full (expect_tx)
#pragma unroll
        for (int i = 5; i < 10; i++) MBARRIER_INIT(smem_u32(&s_mbar[i]), 8);  // empty (8 warps)
    }
    __syncthreads();

    uint32_t fA[4], eA[4];
#pragma unroll
    for (int i = 0; i < 4; i++) { fA[i] = smem_u32(&s_mbar[i]); eA[i] = smem_u32(&s_mbar[5 + i]); }
    const uint32_t fx = smem_u32(&s_mbar[4]), ex = smem_u32(&s_mbar[9]);
    uint32_t Abuf[4];
#pragma unroll
    for (int i = 0; i < 4; i++) Abuf[i] = base + OFF_A + i * 16384;
    const uint32_t XB = base + OFF_XB;

    // =========================== DMA warp ===========================
    if (wid == 8) {
        if (lane == 0) {
            volatile unsigned* cnt[4] = { &g_cnt[grp][0][0], &g_cnt[grp][1][0],
                                          &g_cnt[grp][2][0], &g_cnt[grp][3][0] };
            int peA[4] = {1, 1, 1, 1}, pex = 1;
#pragma unroll 1
            for (int t = 0; t < Tt; t++) {
                const unsigned char (*hsrc)[16384] = g_hblk[t & 1][grp];
                const unsigned target = (unsigned)t * 8u;
                // x tile (no producer dependency)
                MBAR_WAIT(ex, pex); pex ^= 1;
                FENCE_PROXY_ASYNC();
                tma_issue(XB, &g_xblk[t][grp][0], 8192, fx);
                // h chunks 0..3, each in its own buffer -> all 4 TMAs in flight
#pragma unroll
                for (int kc = 0; kc < 4; kc++) {
                    MBAR_WAIT(eA[kc], peA[kc]); peA[kc] ^= 1;
                    unsigned v;
                    do {
                        asm volatile("ld.acquire.gpu.global.u32 %0, [%1];" : "=r"(v) : "l"(cnt[kc]));
                    } while (v < target);
                    FENCE_PROXY_ASYNC();
                    tma_issue(Abuf[kc], &hsrc[kc][0], 16384, fA[kc]);
                }
            }
        }
        return;
    }

    // =========================== compute warps ===========================
    // warp decomposition: mh = M half (32 rows), nh = N half (32 cols), ks = K split
    const int mh = wid & 1, nh = (wid >> 1) & 1, ks = wid >> 2;
    const int m0 = mh * 32;
    const int n0 = nh * 32;
    const uint32_t WhW = base + OFF_WH + n0 * 1024;
    const uint32_t WxW = base + OFF_WX + n0 * 128;
    // dedicated epilogue scratch: two planes [64][68] floats
    float* scr = reinterpret_cast<float*>(bptr + OFF_SCR);
    float* myplane = scr + ks * (64 * 68);

    const int em = tid & 63, eg = tid >> 6;  // epilogue mapping over 256 threads
    float bia[16];
#pragma unroll
    for (int q = 0; q < 16; q++) bia[q] = s_bias[eg * 16 + q];

    const int u0 = nc * 16 + eg * 4;
    const int kcb = u0 >> 7, ucol = u0 & 127;
    const unsigned hoff = (unsigned)em * 256u + ((((unsigned)ucol >> 3) ^ (em & 7)) << 4) + (ucol & 7) * 2u;
    unsigned* mycnt = &g_cnt[grp][nc >> 3][0];

    float cs[4] = {0.f, 0.f, 0.f, 0.f};
    int pfA[4] = {0, 0, 0, 0}, pfx = 0;

#pragma unroll 1
    for (int t = 0; t < Tt; t++) {
        const int wb = (t & 1) ^ 1;

        float acc[2][4][4];
#pragma unroll
        for (int m = 0; m < 2; m++)
#pragma unroll
            for (int a = 0; a < 4; a++)
#pragma unroll
                for (int bq = 0; bq < 4; bq++) acc[m][a][bq] = 0.f;

        // x chunk FIRST — no h dependency, hides h-TMA latency
        MBAR_WAIT(fx, pfx); pfx ^= 1;
        compute_chunk<128, 128, 2>(XB, WxW, 0, ks * 2, acc, lane, m0);
        if (lane == 0) MBARRIER_ARRIVE(ex);
        // h chunks 0..3, each its own buffer, immediate empty arrival
#pragma unroll
        for (int kc = 0; kc < 4; kc++) {
            MBAR_WAIT(fA[kc], pfA[kc]); pfA[kc] ^= 1;
            compute_chunk<256, 1024, 4>(Abuf[kc], WhW, kc * 16, ks * 4, acc, lane, m0);
            if (lane == 0) MBARRIER_ARRIVE(eA[kc]);
        }

        // ---- epilogue (dedicated scratch; 2 bars) ----
        {
            const int r0 = m0 + (lane >> 2), cb = n0 + (lane & 3) * 2;
#pragma unroll
            for (int m = 0; m < 2; m++)
#pragma unroll
                for (int ti = 0; ti < 4; ti++) {
                    *reinterpret_cast<float2*>(&myplane[(r0 + m * 16) * 68 + ti * 8 + cb]) =
                        make_float2(acc[m][ti][0], acc[m][ti][1]);
                    *reinterpret_cast<float2*>(&myplane[(r0 + 8 + m * 16) * 68 + ti * 8 + cb]) =
                        make_float2(acc[m][ti][2], acc[m][ti][3]);
                }
        }
        BAR_COMPUTE();
        {
            __align__(8) __half hh[4];
            float hv4[4];
#pragma unroll
            for (int q = 0; q < 4; q++) {
                float4 v  = *reinterpret_cast<float4*>(&scr[em * 68 + eg * 16 + q * 4]);
                float4 v2 = *reinterpret_cast<float4*>(&scr[64 * 68 + em * 68 + eg * 16 + q * 4]);
                float iv = sigm(v.x + v2.x + bia[q * 4 + 0]);
                float fv = sigm(v.y + v2.y + bia[q * 4 + 1]);
                float gv = tanh_(v.z + v2.z + bia[q * 4 + 2]);
                float ov = sigm(v.w + v2.w + bia[q * 4 + 3]);
                cs[q] = fv * cs[q] + iv * gv;
                float hv = ov * tanh_(cs[q]);
                hv4[q] = hv;
                hh[q] = __float2half(hv);
            }
            unsigned char* dst = &g_hblk[wb][grp][kcb][0] + hoff;
            *reinterpret_cast<uint2*>(dst) = *reinterpret_cast<uint2*>(hh);
            if (t == Tt - 1)
                *reinterpret_cast<float4*>(&g_hfinal[grp * 64 + em][u0]) =
                    make_float4(hv4[0], hv4[1], hv4[2], hv4[3]);
        }
        BAR_COMPUTE();     // all h writes + all scratch reads done before next step
        if (tid == 0 && t < Tt - 1)
            asm volatile("red.release.gpu.global.add.u32 [%0], %1;" :: "l"(mycnt), "r"(1u) : "memory");
    }
}

// ---------------- final FC ----------------
__global__ void fc_kernel(const float* __restrict__ W_fc,
                          const float* __restrict__ b_fc,
                          float* __restrict__ out) {
    int b = threadIdx.x;
    float s = 0.f;
#pragma unroll 8
    for (int k = 0; k < Hh; k++) s += g_hfinal[b][k] * W_fc[k];
    out[b] = s + b_fc[0];
}

extern "C" void kernel_launch(void* const* d_in, const int* in_sizes, int n_in,
                              void* d_out, int out_size) {
    const float* x    = (const float*)d_in[0];
    const float* W_ih = (const float*)d_in[1];
    const float* W_hh = (const float*)d_in[2];
    const float* b_ih = (const float*)d_in[3];
    const float* b_hh = (const float*)d_in[4];
    const float* W_fc = (const float*)d_in[5];
    const float* b_fc = (const float*)d_in[6];
    float* out = (float*)d_out;

    cudaFuncSetAttribute(lstm_kernel, cudaFuncAttributeMaxDynamicSharedMemorySize, DSM_BYTES);

    init_kernel<<<1024, 256>>>(x);
    lstm_kernel<<<128, NTHR, DSM_BYTES>>>(W_ih, W_hh, b_ih, b_hh);
    fc_kernel<<<1, Bb>>>(W_fc, b_fc, out);
}

// round 12
// speedup vs baseline: 1.1422x; 1.0058x over previous
#include <cuda_runtime.h>
#include <cuda_fp16.h>
#include <cstdint>

// ---------------- problem constants ----------------
#define Bb   256
#define Tt   512
#define Ii   64
#define Hh   512
#define NTHR 288     // 8 compute warps (2M x 2N x 2Ksplit, tile M32xN32) + 1 DMA warp

// SMEM layout offsets (from 1024-aligned base)
#define OFF_WH   0            // W_hh slice (fp16): [64 c][1024 B] = 64KB
#define OFF_WX   65536        // W_ih slice: [64 c][128 B] = 8KB
#define OFF_A    73728        // 4 h chunk bufs, 16KB each (fp16)
#define OFF_XB   139264       // x buf: 8KB
#define OFF_SCR  147456       // epilogue scratch: 2 planes x 64x68 f32 = 34816 B
#define DSM_BYTES (182272 + 1024)

// ---------------- persistent device state ----------------
// h tile layout: [buf][group][kchunk][16KB]; group = half*2 + mtile (64 batch rows)
// chunk = 64 rows x 128 units fp16 (256B/row), 16B-chunk swizzle
__device__ __align__(1024) unsigned char g_hblk[2][4][4][16384];
// x tile layout: [t][group][8KB] = 64 rows x 64 fp16 (128B/row), swizzled
__device__ __align__(1024) unsigned char g_xblk[Tt][4][8192];
__device__ float    g_hfinal[Bb][Hh];
__device__ unsigned g_cnt[4][4][16];   // [group][kchunk], padded to 64B

// ---------------- PTX helpers ----------------
__device__ __forceinline__ uint32_t smem_u32(const void* p) {
    uint32_t a;
    asm("{ .reg .u64 t; cvta.to.shared.u64 t, %1; cvt.u32.u64 %0, t; }" : "=r"(a) : "l"(p));
    return a;
}
#define MBARRIER_INIT(sa, cnt) \
    asm volatile("mbarrier.init.shared.b64 [%0], %1;" :: "r"((uint32_t)(sa)), "r"((uint32_t)(cnt)) : "memory")
#define MBARRIER_ARRIVE(sa) \
    asm volatile("mbarrier.arrive.shared.b64 _, [%0];" :: "r"((uint32_t)(sa)) : "memory")
#define MBAR_WAIT(sa, ph) do { \
    asm volatile("{\n\t.reg .pred P1;\n\tWL%=:\n\t" \
        "mbarrier.try_wait.parity.acquire.cta.shared::cta.b64 P1, [%0], %1, 0x989680;\n\t" \
        "@P1 bra.uni WD%=;\n\tbra.uni WL%=;\n\tWD%=:\n\t}" \
        :: "r"((uint32_t)(sa)), "r"((uint32_t)(ph)) : "memory"); \
} while (0)
#define FENCE_PROXY_ASYNC() asm volatile("fence.proxy.async;" ::: "memory")

__device__ __forceinline__ void tma_issue(uint32_t dst, const void* src, uint32_t bytes, uint32_t mbar) {
    asm volatile("mbarrier.arrive.expect_tx.shared.b64 _, [%0], %1;"
                 :: "r"(mbar), "r"(bytes) : "memory");
    asm volatile("cp.async.bulk.shared::cta.global.mbarrier::complete_tx::bytes [%0], [%1], %2, [%3];"
                 :: "r"(dst), "l"(src), "r"(bytes), "r"(mbar) : "memory");
}
__device__ __forceinline__ void ldsm4(uint32_t& a, uint32_t& b, uint32_t& c, uint32_t& d, uint32_t addr) {
    asm volatile("ldmatrix.sync.aligned.m8n8.x4.shared.b16 {%0,%1,%2,%3}, [%4];"
                 : "=r"(a), "=r"(b), "=r"(c), "=r"(d) : "r"(addr));
}
// f32-accum fp16 MMA (x chunk)
__device__ __forceinline__ void mma16816(float* c, uint32_t a0, uint32_t a1, uint32_t a2, uint32_t a3,
                                         uint32_t b0, uint32_t b1) {
    asm volatile("mma.sync.aligned.m16n8k16.row.col.f32.f16.f16.f32 "
                 "{%0,%1,%2,%3}, {%4,%5,%6,%7}, {%8,%9}, {%0,%1,%2,%3};"
                 : "+f"(c[0]), "+f"(c[1]), "+f"(c[2]), "+f"(c[3])
                 : "r"(a0), "r"(a1), "r"(a2), "r"(a3), "r"(b0), "r"(b1));
}
// f16-accum fp16 MMA (h chunks) — 2 D registers (4 halves)
__device__ __forceinline__ void mma16816h(uint32_t* c, uint32_t a0, uint32_t a1, uint32_t a2, uint32_t a3,
                                          uint32_t b0, uint32_t b1) {
    asm volatile("mma.sync.aligned.m16n8k16.row.col.f16.f16.f16.f16 "
                 "{%0,%1}, {%2,%3,%4,%5}, {%6,%7}, {%0,%1};"
                 : "+r"(c[0]), "+r"(c[1])
                 : "r"(a0), "r"(a1), "r"(a2), "r"(a3), "r"(b0), "r"(b1));
}
#define BAR_COMPUTE() asm volatile("bar.sync 1, 256;" ::: "memory")

// ---------------- activations ----------------
__device__ __forceinline__ float sigm(float x) { return __fdividef(1.f, 1.f + __expf(-x)); }
__device__ __forceinline__ float tanh_(float x) {
    x = fminf(fmaxf(x, -15.f), 15.f);
    float e = __expf(2.f * x);
    return __fdividef(e - 1.f, e + 1.f);
}

// ---------------- h-chunk GEMM: fp16 accum, warp tile M32xN32, K-split ----------------
// A tile [64 rows x 128 k] fp16 at Abase (256B rows), W rows 1024B.
// Accumulates into f16 frags acc16[2][4][2]; caller promotes to f32.
template<int NKH>
__device__ __forceinline__ void compute_chunk_h16(uint32_t Abase, uint32_t Whi,
                                                  int kw0, int s0, uint32_t (&acc16)[2][4][2],
                                                  int lane, int m0) {
    const int rA = m0 + (lane & 15);
    const int kA = lane >> 4;
    const int xr = lane & 7;
    const int cB = (lane & 7) + ((lane & 16) >> 1);
    const int kB = (lane >> 3) & 1;
#pragma unroll
    for (int si = 0; si < NKH; si++) {
        const int s = s0 + si;
        const int kcA = s * 2;
        uint32_t aaddr = Abase + rA * 256 + (((kcA + kA) ^ xr) << 4);
        uint32_t a0[4], a1[4];
        ldsm4(a0[0], a0[1], a0[2], a0[3], aaddr);
        ldsm4(a1[0], a1[1], a1[2], a1[3], aaddr + 16 * 256);
        const int kcW = kw0 + s * 2;
        uint32_t b01 = Whi + cB * 1024 + (((kcW + kB) ^ xr) << 4);
        uint32_t bh[8];
        ldsm4(bh[0], bh[1], bh[2], bh[3], b01);
        ldsm4(bh[4], bh[5], bh[6], bh[7], b01 + 16 * 1024);
#pragma unroll
        for (int ti = 0; ti < 4; ti++) {
            mma16816h(acc16[0][ti], a0[0], a0[1], a0[2], a0[3], bh[2 * ti], bh[2 * ti + 1]);
            mma16816h(acc16[1][ti], a1[0], a1[1], a1[2], a1[3], bh[2 * ti], bh[2 * ti + 1]);
        }
    }
}

// ---------------- x-chunk GEMM: f32 accum ----------------
template<int RS, int WR, int NKH>
__device__ __forceinline__ void compute_chunk(uint32_t Abase, uint32_t Whi,
                                              int kw0, int s0, float (&acc)[2][4][4],
                                              int lane, int m0) {
    const int rA = m0 + (lane & 15);
    const int kA = lane >> 4;
    const int xr = lane & 7;
    const int cB = (lane & 7) + ((lane & 16) >> 1);
    const int kB = (lane >> 3) & 1;
#pragma unroll
    for (int si = 0; si < NKH; si++) {
        const int s = s0 + si;
        const int kcA = s * 2;
        uint32_t aaddr = Abase + rA * RS + (((kcA + kA) ^ xr) << 4);
        uint32_t a0[4], a1[4];
        ldsm4(a0[0], a0[1], a0[2], a0[3], aaddr);
        ldsm4(a1[0], a1[1], a1[2], a1[3], aaddr + 16 * RS);
        const int kcW = kw0 + s * 2;
        uint32_t b01 = Whi + cB * WR + (((kcW + kB) ^ xr) << 4);
        uint32_t bh[8];
        ldsm4(bh[0], bh[1], bh[2], bh[3], b01);
        ldsm4(bh[4], bh[5], bh[6], bh[7], b01 + 16 * WR);
#pragma unroll
        for (int ti = 0; ti < 4; ti++) {
            mma16816(acc[0][ti], a0[0], a0[1], a0[2], a0[3], bh[2 * ti], bh[2 * ti + 1]);
            mma16816(acc[1][ti], a1[0], a1[1], a1[2], a1[3], bh[2 * ti], bh[2 * ti + 1]);
        }
    }
}

// ---------------- init: zero h buf0, reset counters, x -> fp16 tile layout ----------------
__global__ void init_kernel(const float* __restrict__ x) {
    int idx = blockIdx.x * blockDim.x + threadIdx.x;
    int stride = gridDim.x * blockDim.x;
    uint32_t* hz = reinterpret_cast<uint32_t*>(&g_hblk[0][0][0][0]);
    for (int i = idx; i < 4 * 4 * 16384 / 4; i += stride) hz[i] = 0u;
    for (int i = idx; i < Bb * Tt * Ii; i += stride) {
        int ii = i & 63;
        int t  = (i >> 6) & 511;
        int b  = i >> 15;
        int grp = b >> 6, m = b & 63;
        unsigned off = (unsigned)m * 128u + ((((unsigned)ii >> 3) ^ (m & 7)) << 4) + (ii & 7) * 2u;
        *reinterpret_cast<__half*>(&g_xblk[t][grp][off]) = __float2half(x[i]);
    }
    if (idx < 16) g_cnt[idx >> 2][idx & 3][0] = 0u;
}

// ---------------- persistent LSTM: warp-specialized, 4-deep TMA, fp16-accum chunks ----------------
__global__ void __launch_bounds__(NTHR, 1) lstm_kernel(
    const float* __restrict__ W_ih,   // [2048, 64]
    const float* __restrict__ W_hh,   // [2048, 512]
    const float* __restrict__ b_ih,
    const float* __restrict__ b_hh)
{
    extern __shared__ char dsm[];
    // mbarriers: 0..3 = full A[kc], 4 = full X, 5..8 = empty A[kc], 9 = empty X
    __shared__ __align__(8) unsigned long long s_mbar[10];
    __shared__ float s_bias[64];

    const int tid  = threadIdx.x;
    const int lane = tid & 31;
    const int wid  = tid >> 5;
    const int grp  = blockIdx.x >> 5;       // owns 64 batch rows
    const int nc   = blockIdx.x & 31;       // gate cols [nc*64, nc*64+64) -> 16 units

    uint32_t raw = smem_u32(dsm);
    uint32_t base = (raw + 1023u) & ~1023u;
    char* bptr = dsm + (base - raw);

    // ---- stage W slices (once), fp16, swizzled ----
    for (int idx = tid; idx < 64 * Hh; idx += NTHR) {
        int c = idx >> 9, k = idx & 511;
        int row = (c & 3) * Hh + nc * 16 + (c >> 2);
        float w = W_hh[(size_t)row * Hh + k];
        unsigned off = (unsigned)c * 1024u + ((((unsigned)k >> 3) ^ (c & 7)) << 4) + (k & 7) * 2u;
        *reinterpret_cast<__half*>(bptr + OFF_WH + off) = __float2half(w);
    }
    for (int idx = tid; idx < 64 * Ii; idx += NTHR) {
        int c = idx >> 6, k = idx & 63;
        int row = (c & 3) * Hh + nc * 16 + (c >> 2);
        float w = W_ih[(size_t)row * Ii + k];
        unsigned off = (unsigned)c * 128u + ((((unsigned)k >> 3) ^ (c & 7)) << 4) + (k & 7) * 2u;
        *reinterpret_cast<__half*>(bptr + OFF_WX + off) = __float2half(w);
    }
    if (tid < 64) {
        int row = (tid & 3) * Hh + nc * 16 + (tid >> 2);
        s_bias[tid] = b_ih[row] + b_hh[row];
    }
    if (tid == 0) {
#pragma unroll
        for (int i = 0; i < 5; i++) MBARRIER_INIT(smem_u32(&s_mbar[i]), 1);   // full (expect_tx)
#pragma unroll
        for (int i = 5; i < 10; i++) MBARRIER_INIT(smem_u32(&s_mbar[i]), 8);  // empty (8 warps)
    }
    __syncthreads();

    uint32_t fA[4], eA[4];
#pragma unroll
    for (int i = 0; i < 4; i++) { fA[i] = smem_u32(&s_mbar[i]); eA[i] = smem_u32(&s_mbar[5 + i]); }
    const uint32_t fx = smem_u32(&s_mbar[4]), ex = smem_u32(&s_mbar[9]);
    uint32_t Abuf[4];
#pragma unroll
    for (int i = 0; i < 4; i++) Abuf[i] = base + OFF_A + i * 16384;
    const uint32_t XB = base + OFF_XB;

    // =========================== DMA warp ===========================
    if (wid == 8) {
        if (lane == 0) {
            volatile unsigned* cnt[4] = { &g_cnt[grp][0][0], &g_cnt[grp][1][0],
                                          &g_cnt[grp][2][0], &g_cnt[grp][3][0] };
            int peA[4] = {1, 1, 1, 1}, pex = 1;
#pragma unroll 1
            for (int t = 0; t < Tt; t++) {
                const unsigned char (*hsrc)[16384] = g_hblk[t & 1][grp];
                const unsigned target = (unsigned)t * 8u;
                // x tile (no producer dependency)
                MBAR_WAIT(ex, pex); pex ^= 1;
                FENCE_PROXY_ASYNC();
                tma_issue(XB, &g_xblk[t][grp][0], 8192, fx);
                // h chunks 0..3, each in its own buffer -> all 4 TMAs in flight
#pragma unroll
                for (int kc = 0; kc < 4; kc++) {
                    MBAR_WAIT(eA[kc], peA[kc]); peA[kc] ^= 1;
                    unsigned v;
                    do {
                        asm volatile("ld.acquire.gpu.global.u32 %0, [%1];" : "=r"(v) : "l"(cnt[kc]));
                    } while (v < target);
                    FENCE_PROXY_ASYNC();
                    tma_issue(Abuf[kc], &hsrc[kc][0], 16384, fA[kc]);
                }
            }
        }
        return;
    }

    // =========================== compute warps ===========================
    // warp decomposition: mh = M half (32 rows), nh = N half (32 cols), ks = K split
    const int mh = wid & 1, nh = (wid >> 1) & 1, ks = wid >> 2;
    const int m0 = mh * 32;
    const int n0 = nh * 32;
    const uint32_t WhW = base + OFF_WH + n0 * 1024;
    const uint32_t WxW = base + OFF_WX + n0 * 128;
    // dedicated epilogue scratch: two planes [64][68] floats
    float* scr = reinterpret_cast<float*>(bptr + OFF_SCR);
    float* myplane = scr + ks * (64 * 68);

    const int em = tid & 63, eg = tid >> 6;  // epilogue mapping over 256 threads
    float bia[16];
#pragma unroll
    for (int q = 0; q < 16; q++) bia[q] = s_bias[eg * 16 + q];

    const int u0 = nc * 16 + eg * 4;
    const int kcb = u0 >> 7, ucol = u0 & 127;
    const unsigned hoff = (unsigned)em * 256u + ((((unsigned)ucol >> 3) ^ (em & 7)) << 4) + (ucol & 7) * 2u;
    unsigned* mycnt = &g_cnt[grp][nc >> 3][0];

    float cs[4] = {0.f, 0.f, 0.f, 0.f};
    int pfA[4] = {0, 0, 0, 0}, pfx = 0;

#pragma unroll 1
    for (int t = 0; t < Tt; t++) {
        const int wb = (t & 1) ^ 1;

        float acc[2][4][4];
#pragma unroll
        for (int m = 0; m < 2; m++)
#pragma unroll
            for (int a = 0; a < 4; a++)
#pragma unroll
                for (int bq = 0; bq < 4; bq++) acc[m][a][bq] = 0.f;

        // x chunk FIRST — no h dependency, hides h-TMA latency (f32 accum)
        MBAR_WAIT(fx, pfx); pfx ^= 1;
        compute_chunk<128, 128, 2>(XB, WxW, 0, ks * 2, acc, lane, m0);
        if (lane == 0) MBARRIER_ARRIVE(ex);

        // h chunks 0..3: fp16 accum per chunk, promote to f32 after each
#pragma unroll
        for (int kc = 0; kc < 4; kc++) {
            MBAR_WAIT(fA[kc], pfA[kc]); pfA[kc] ^= 1;
            uint32_t acc16[2][4][2];
#pragma unroll
            for (int m = 0; m < 2; m++)
#pragma unroll
                for (int a = 0; a < 4; a++) { acc16[m][a][0] = 0u; acc16[m][a][1] = 0u; }
            compute_chunk_h16<4>(Abuf[kc], WhW, kc * 16, ks * 4, acc16, lane, m0);
            if (lane == 0) MBARRIER_ARRIVE(eA[kc]);
#pragma unroll
            for (int m = 0; m < 2; m++)
#pragma unroll
                for (int a = 0; a < 4; a++) {
                    float2 lo = __half22float2(*reinterpret_cast<__half2*>(&acc16[m][a][0]));
                    float2 hi = __half22float2(*reinterpret_cast<__half2*>(&acc16[m][a][1]));
                    acc[m][a][0] += lo.x; acc[m][a][1] += lo.y;
                    acc[m][a][2] += hi.x; acc[m][a][3] += hi.y;
                }
        }

        // ---- epilogue (dedicated scratch; 2 bars) ----
        {
            const int r0 = m0 + (lane >> 2), cb = n0 + (lane & 3) * 2;
#pragma unroll
            for (int m = 0; m < 2; m++)
#pragma unroll
                for (int ti = 0; ti < 4; ti++) {
                    *reinterpret_cast<float2*>(&myplane[(r0 + m * 16) * 68 + ti * 8 + cb]) =
                        make_float2(acc[m][ti][0], acc[m][ti][1]);
                    *reinterpret_cast<float2*>(&myplane[(r0 + 8 + m * 16) * 68 + ti * 8 + cb]) =
                        make_float2(acc[m][ti][2], acc[m][ti][3]);
                }
        }
        BAR_COMPUTE();
        {
            __align__(8) __half hh[4];
            float hv4[4];
#pragma unroll
            for (int q = 0; q < 4; q++) {
                float4 v  = *reinterpret_cast<float4*>(&scr[em * 68 + eg * 16 + q * 4]);
                float4 v2 = *reinterpret_cast<float4*>(&scr[64 * 68 + em * 68 + eg * 16 + q * 4]);
                float iv = sigm(v.x + v2.x + bia[q * 4 + 0]);
                float fv = sigm(v.y + v2.y + bia[q * 4 + 1]);
                float gv = tanh_(v.z + v2.z + bia[q * 4 + 2]);
                float ov = sigm(v.w + v2.w + bia[q * 4 + 3]);
                cs[q] = fv * cs[q] + iv * gv;
                float hv = ov * tanh_(cs[q]);
                hv4[q] = hv;
                hh[q] = __float2half(hv);
            }
            unsigned char* dst = &g_hblk[wb][grp][kcb][0] + hoff;
            *reinterpret_cast<uint2*>(dst) = *reinterpret_cast<uint2*>(hh);
            if (t == Tt - 1)
                *reinterpret_cast<float4*>(&g_hfinal[grp * 64 + em][u0]) =
                    make_float4(hv4[0], hv4[1], hv4[2], hv4[3]);
        }
        BAR_COMPUTE();     // all h writes + all scratch reads done before next step
        if (tid == 0 && t < Tt - 1)
            asm volatile("red.release.gpu.global.add.u32 [%0], %1;" :: "l"(mycnt), "r"(1u) : "memory");
    }
}

// ---------------- final FC ----------------
__global__ void fc_kernel(const float* __restrict__ W_fc,
                          const float* __restrict__ b_fc,
                          float* __restrict__ out) {
    int b = threadIdx.x;
    float s = 0.f;
#pragma unroll 8
    for (int k = 0; k < Hh; k++) s += g_hfinal[b][k] * W_fc[k];
    out[b] = s + b_fc[0];
}

// ---------------- probe: shifts ncu -s 5 phase so lstm_kernel can be captured ----------------
__global__ void probe_kernel() {}

extern "C" void kernel_launch(void* const* d_in, const int* in_sizes, int n_in,
                              void* d_out, int out_size) {
    const float* x    = (const float*)d_in[0];
    const float* W_ih = (const float*)d_in[1];
    const float* W_hh = (const float*)d_in[2];
    const float* b_ih = (const float*)d_in[3];
    const float* b_hh = (const float*)d_in[4];
    const float* W_fc = (const float*)d_in[5];
    const float* b_fc = (const float*)d_in[6];
    float* out = (float*)d_out;

    cudaFuncSetAttribute(lstm_kernel, cudaFuncAttributeMaxDynamicSharedMemorySize, DSM_BYTES);

    init_kernel<<<1024, 256>>>(x);
    lstm_kernel<<<128, NTHR, DSM_BYTES>>>(W_ih, W_hh, b_ih, b_hh);
    fc_kernel<<<1, Bb>>>(W_fc, b_fc, out);
    probe_kernel<<<1, 32>>>();
}